// round 8
// baseline (speedup 1.0000x reference)
#include <cuda_runtime.h>
#include <cuda_bf16.h>
#include <cstdint>

// Problem constants
#define BATCH   4
#define T_TXT   2048
#define T_IMG   8
#define N_LAT   64
#define DIM     2048
#define DIM_VIS 1024
#define HEADS   8
#define DIM_HEAD 64
#define INNER   (HEADS * DIM_HEAD)      // 512
#define ROWS    (BATCH * T_TXT)         // 8192
#define KVROWS  (BATCH * T_IMG * N_LAT) // 2048
#define LN_EPS  1e-5f

// k-permutation within each 8-group (applied identically to A and B k-dims)
#define PERM8(j) ((((j) & 3) * 2) + (((j) >> 2) & 1))
#define PIDX(c)  (((c) & ~7) | PERM8((c) & 7))

// ---------------- scratch (static device, no allocs) ----------------
__device__ float g_xn[ROWS * DIM];          // k-permuted along DIM
__device__ float g_q [ROWS * INNER];
__device__ float g_kv[KVROWS * 2 * INNER];
__device__ float g_ao[ROWS * INNER];        // k-permuted along INNER
__device__ float g_wq_t [INNER * DIM];      // [n][k] transposed, k-permuted
__device__ float g_wkv_t[2 * INNER * DIM_VIS];
__device__ float g_wout_t[DIM * INNER];
__device__ float g_media_t[KVROWS * DIM_VIS]; // k-permuted along DIM_VIS
__device__ int   g_qlist[BATCH][9][T_TXT];
__device__ int   g_qcount[BATCH][9];

__device__ __forceinline__ uint32_t f2tf32(float f) {
    uint32_t r;
    asm("cvt.rna.tf32.f32 %0, %1;" : "=r"(r) : "f"(f));
    return r;
}
__device__ __forceinline__ float rnd_tf32(float f) { return __uint_as_float(f2tf32(f)); }
__device__ __forceinline__ uint32_t smem_u32(const void* p) {
    uint32_t a;
    asm("{ .reg .u64 t; cvta.to.shared.u64 t, %1; cvt.u32.u64 %0, t; }" : "=r"(a) : "l"(p));
    return a;
}

#define CP_ASYNC16(dst, src) \
    asm volatile("cp.async.cg.shared.global [%0], [%1], 16;" :: "r"(dst), "l"(src))
#define CP_COMMIT() asm volatile("cp.async.commit_group;" ::: "memory")
#define CP_WAIT1()  asm volatile("cp.async.wait_group 1;" ::: "memory")

// ---------------- cp.async pipelined TF32 GEMM (LDS.64 fragments) ----------------
// C[M,N] = A[M,K] @ Bt[N,K]^T. A, Bt row-major fp32 pre-rounded tf32, k-permuted.
// Block 128x128, KT=32, 256 threads (8 warps), warp tile 64x32, 3 stages.
#define KT 32
#define PROW 40                              // floats per smem row (32 + 8 pad)
#define STG_BYTES (128 * PROW * 4)           // 20480 per operand
#define STAGES 3
#define SMEM_BYTES (STAGES * 2 * STG_BYTES)  // 122880

__global__ __launch_bounds__(256) void tf32gemm_pipe(const float* __restrict__ A,
                                                     const float* __restrict__ Bt,
                                                     float* __restrict__ C,
                                                     int M, int N, int K) {
    extern __shared__ char smem[];
    const uint32_t sb = smem_u32(smem);
    const int tid = threadIdx.x;
    const int lane = tid & 31, warp = tid >> 5;
    const int tq = lane & 3, tg = lane >> 2;
    const int wm = (warp >> 2) * 64;   // 0/64
    const int wn = (warp & 3) * 32;    // 0/32/64/96

    const int mblk = blockIdx.y * 128;
    const int nblk = blockIdx.x * 128;
    const float* Ab = A + (size_t)mblk * K;
    const float* Bb = Bt + (size_t)nblk * K;

    float acc[4][4][4];
    #pragma unroll
    for (int mf = 0; mf < 4; mf++)
        #pragma unroll
        for (int nf = 0; nf < 4; nf++)
            #pragma unroll
            for (int i = 0; i < 4; i++) acc[mf][nf][i] = 0.f;

    const int nK = K / KT;

    // A and B tiles are structurally identical: 128 rows x 8 16B-chunks.
    auto issue = [&](int s, int c) {
        const uint32_t sa = sb + s * 2 * STG_BYTES;
        const uint32_t sB = sa + STG_BYTES;
        const int k0 = c * KT;
        #pragma unroll
        for (int i = 0; i < 4; i++) {
            int id = tid + i * 256;             // 0..1023
            int row = id >> 3, c4 = id & 7;
            CP_ASYNC16(sa + row * (PROW * 4) + c4 * 16,
                       Ab + (size_t)row * K + k0 + c4 * 4);
            CP_ASYNC16(sB + row * (PROW * 4) + c4 * 16,
                       Bb + (size_t)row * K + k0 + c4 * 4);
        }
    };

    issue(0, 0); CP_COMMIT();
    if (nK > 1) issue(1, 1);
    CP_COMMIT();

    int buf = 0;
    for (int c = 0; c < nK; c++) {
        CP_WAIT1();
        __syncthreads();
        if (c + 2 < nK) issue((c + 2) % STAGES, c + 2);
        CP_COMMIT();

        const float2* As2 = (const float2*)(smem + buf * 2 * STG_BYTES);
        const float2* Bs2 = (const float2*)(smem + buf * 2 * STG_BYTES + STG_BYTES);

        #pragma unroll
        for (int ks = 0; ks < KT; ks += 8) {
            // k-positions ks+2tq, ks+2tq+1 hold original k = ks+tq, ks+tq+4
            float2 am0[4], am8[4], bb[4];
            #pragma unroll
            for (int mf = 0; mf < 4; mf++) {
                const int m0 = wm + mf * 16 + tg;
                am0[mf] = As2[m0 * (PROW / 2) + ks / 2 + tq];
                am8[mf] = As2[(m0 + 8) * (PROW / 2) + ks / 2 + tq];
            }
            #pragma unroll
            for (int nf = 0; nf < 4; nf++)
                bb[nf] = Bs2[(wn + nf * 8 + tg) * (PROW / 2) + ks / 2 + tq];

            #pragma unroll
            for (int mf = 0; mf < 4; mf++)
                #pragma unroll
                for (int nf = 0; nf < 4; nf++) {
                    asm volatile(
                        "mma.sync.aligned.m16n8k8.row.col.f32.tf32.tf32.f32 "
                        "{%0,%1,%2,%3}, {%4,%5,%6,%7}, {%8,%9}, {%0,%1,%2,%3};"
                        : "+f"(acc[mf][nf][0]), "+f"(acc[mf][nf][1]),
                          "+f"(acc[mf][nf][2]), "+f"(acc[mf][nf][3])
                        : "r"(__float_as_uint(am0[mf].x)), "r"(__float_as_uint(am8[mf].x)),
                          "r"(__float_as_uint(am0[mf].y)), "r"(__float_as_uint(am8[mf].y)),
                          "r"(__float_as_uint(bb[nf].x)),  "r"(__float_as_uint(bb[nf].y)));
                }
        }
        __syncthreads();
        buf = (buf + 1) % STAGES;
    }

    #pragma unroll
    for (int mf = 0; mf < 4; mf++) {
        const int row0 = mblk + wm + mf * 16 + tg;
        #pragma unroll
        for (int nf = 0; nf < 4; nf++) {
            const int col = nblk + wn + nf * 8 + 2 * tq;
            *(float2*)(C + (size_t)row0 * N + col) =
                make_float2(acc[mf][nf][0], acc[mf][nf][1]);
            *(float2*)(C + (size_t)(row0 + 8) * N + col) =
                make_float2(acc[mf][nf][2], acc[mf][nf][3]);
        }
    }
}

// ---------------- weight transpose + tf32 round + k-permute ----------------
// in: [K][N] row-major. out: [N][K] row-major with PIDX applied to k.
__global__ __launch_bounds__(256) void wtrans_kernel(const float* __restrict__ in,
                                                     float* __restrict__ out,
                                                     int K, int N) {
    __shared__ float t[32][33];
    const int k0 = blockIdx.y * 32, n0 = blockIdx.x * 32;
    const int tx = threadIdx.x & 31, ty = threadIdx.x >> 5;  // 32x8
    #pragma unroll
    for (int i = ty; i < 32; i += 8)
        t[i][tx] = in[(size_t)(k0 + i) * N + n0 + tx];
    __syncthreads();
    #pragma unroll
    for (int i = ty; i < 32; i += 8) {
        const int n = n0 + i, k = k0 + tx;
        out[(size_t)n * K + PIDX(k)] = rnd_tf32(t[tx][i]);
    }
}

// ---------------- media: tf32 round + k-permute (within-row groups of 8) ----------------
__global__ __launch_bounds__(256) void cvt_perm_kernel(const float* __restrict__ in,
                                                       float* __restrict__ out, int n4) {
    int i = blockIdx.x * 256 + threadIdx.x;
    if (i < n4) {
        float4 v = ((const float4*)in)[i];
        const int base = i * 4;
        out[PIDX(base + 0)] = rnd_tf32(v.x);
        out[PIDX(base + 1)] = rnd_tf32(v.y);
        out[PIDX(base + 2)] = rnd_tf32(v.z);
        out[PIDX(base + 3)] = rnd_tf32(v.w);
    }
}

// ---------------- LayerNorm (single pass, tf32-rounded, k-permuted output) ----------------
__global__ __launch_bounds__(256) void ln_kernel(const float* __restrict__ x,
                                                 const float* __restrict__ gamma,
                                                 const float* __restrict__ beta) {
    const int row = blockIdx.x;
    const float4* xr = (const float4*)(x + (size_t)row * DIM);
    float* out = g_xn + (size_t)row * DIM;
    const int tid = threadIdx.x;

    __shared__ float reds[256], redq[256];
    float s = 0.f, sq = 0.f;
    #pragma unroll
    for (int c = tid; c < DIM / 4; c += 256) {
        float4 v = xr[c];
        s  += v.x + v.y + v.z + v.w;
        sq += v.x * v.x + v.y * v.y + v.z * v.z + v.w * v.w;
    }
    reds[tid] = s; redq[tid] = sq; __syncthreads();
    for (int o = 128; o > 0; o >>= 1) {
        if (tid < o) { reds[tid] += reds[tid + o]; redq[tid] += redq[tid + o]; }
        __syncthreads();
    }
    const float mu = reds[0] * (1.0f / DIM);
    const float var = redq[0] * (1.0f / DIM) - mu * mu;
    const float rstd = rsqrtf(var + LN_EPS);

    const float4* g4 = (const float4*)gamma;
    const float4* b4 = (const float4*)beta;
    #pragma unroll
    for (int c = tid; c < DIM / 4; c += 256) {
        float4 v = xr[c], g = g4[c], bb = b4[c];
        const int base = c * 4;
        out[PIDX(base + 0)] = rnd_tf32((v.x - mu) * rstd * g.x + bb.x);
        out[PIDX(base + 1)] = rnd_tf32((v.y - mu) * rstd * g.y + bb.y);
        out[PIDX(base + 2)] = rnd_tf32((v.z - mu) * rstd * g.z + bb.z);
        out[PIDX(base + 3)] = rnd_tf32((v.w - mu) * rstd * g.w + bb.w);
    }
}

// ---------------- parallel build of per-(b,tt) query lists ----------------
__global__ __launch_bounds__(256) void build_lists2(const int* __restrict__ locs) {
    const int b = blockIdx.x;
    const int tid = threadIdx.x;
    __shared__ int ssum[256];
    __shared__ int cnt[9];

    const int base = tid * 8;
    int v[8];
    int s = 0;
    #pragma unroll
    for (int j = 0; j < 8; j++) { v[j] = locs[b * T_TXT + base + j]; s += v[j]; }
    ssum[tid] = s;
    if (tid < 9) cnt[tid] = 0;
    __syncthreads();
    for (int off = 1; off < 256; off <<= 1) {
        int t = (tid >= off) ? ssum[tid - off] : 0;
        __syncthreads();
        ssum[tid] += t;
        __syncthreads();
    }
    int run = ssum[tid] - s;
    #pragma unroll
    for (int j = 0; j < 8; j++) {
        run += v[j];
        int p = atomicAdd(&cnt[run], 1);
        g_qlist[b][run][p] = base + j;
    }
    __syncthreads();
    if (tid < 9) g_qcount[b][tid] = cnt[tid];
}

// ---------------- masked chunk attention (tf32-rounded, k-permuted output) ----------------
__global__ __launch_bounds__(256) void attn_kernel() {
    const int blk = blockIdx.x;                 // b*72 + h*9 + tt
    const int b = blk / 72;
    const int h = (blk / 9) % 8;
    const int tt = blk % 9;
    const int cnt = g_qcount[b][tt];
    if (cnt == 0) return;

    const int lane = threadIdx.x & 31;
    const int warp = threadIdx.x >> 5;

    if (tt == 0) {
        for (int qi = warp; qi < cnt; qi += 8) {
            int i = g_qlist[b][0][qi];
            float* dst = g_ao + (size_t)(b * T_TXT + i) * INNER + h * DIM_HEAD;
            dst[lane] = 0.f; dst[lane + 32] = 0.f;
        }
        return;
    }

    __shared__ float ksh[64][65];
    __shared__ float vsh[64][65];
    const int base = b * 512 + (tt - 1) * 64;
    for (int idx = threadIdx.x; idx < 4096; idx += 256) {
        int r = idx >> 6, c = idx & 63;
        const float* kvr = g_kv + (size_t)(base + r) * (2 * INNER);
        ksh[r][c] = kvr[h * DIM_HEAD + c];
        vsh[r][c] = kvr[INNER + h * DIM_HEAD + c];
    }
    __syncthreads();

    const float scale = 0.125f;
    for (int qi = warp; qi < cnt; qi += 8) {
        const int i = g_qlist[b][tt][qi];
        const float* qr = g_q + (size_t)(b * T_TXT + i) * INNER + h * DIM_HEAD;
        const float q0 = qr[lane] * scale;
        const float q1 = qr[lane + 32] * scale;

        float s0 = 0.f, s1 = 0.f;
        #pragma unroll
        for (int d = 0; d < 32; d++) {
            float qd = __shfl_sync(0xffffffffu, q0, d);
            s0 += qd * ksh[lane][d];
            s1 += qd * ksh[lane + 32][d];
        }
        #pragma unroll
        for (int d = 0; d < 32; d++) {
            float qd = __shfl_sync(0xffffffffu, q1, d);
            s0 += qd * ksh[lane][d + 32];
            s1 += qd * ksh[lane + 32][d + 32];
        }
        float m = fmaxf(s0, s1);
        #pragma unroll
        for (int o = 16; o > 0; o >>= 1) m = fmaxf(m, __shfl_xor_sync(0xffffffffu, m, o));
        float p0 = __expf(s0 - m), p1 = __expf(s1 - m);
        float sum = p0 + p1;
        #pragma unroll
        for (int o = 16; o > 0; o >>= 1) sum += __shfl_xor_sync(0xffffffffu, sum, o);
        const float inv = 1.f / sum;
        p0 *= inv; p1 *= inv;

        float o0 = 0.f, o1 = 0.f;
        #pragma unroll
        for (int j = 0; j < 32; j++) {
            float pa = __shfl_sync(0xffffffffu, p0, j);
            float pb = __shfl_sync(0xffffffffu, p1, j);
            o0 += pa * vsh[j][lane]      + pb * vsh[j + 32][lane];
            o1 += pa * vsh[j][lane + 32] + pb * vsh[j + 32][lane + 32];
        }
        float* dst = g_ao + (size_t)(b * T_TXT + i) * INNER + h * DIM_HEAD;
        dst[PIDX(lane)]      = rnd_tf32(o0);
        dst[PIDX(lane + 32)] = rnd_tf32(o1);
    }
}

// ---------------- launch ----------------
extern "C" void kernel_launch(void* const* d_in, const int* in_sizes, int n_in,
                              void* d_out, int out_size) {
    const float* x     = (const float*)d_in[0];
    const float* media = (const float*)d_in[1];
    const int*   locs  = (const int*)d_in[2];
    const float* gamma = (const float*)d_in[3];
    const float* beta  = (const float*)d_in[4];
    const float* Wq    = (const float*)d_in[5];
    const float* Wkv   = (const float*)d_in[6];
    const float* Wout  = (const float*)d_in[7];
    float*       out   = (float*)d_out;

    float *p_xn, *p_q, *p_kv, *p_ao, *p_wq, *p_wkv, *p_wout, *p_media;
    cudaGetSymbolAddress((void**)&p_xn, g_xn);
    cudaGetSymbolAddress((void**)&p_q,  g_q);
    cudaGetSymbolAddress((void**)&p_kv, g_kv);
    cudaGetSymbolAddress((void**)&p_ao, g_ao);
    cudaGetSymbolAddress((void**)&p_wq, g_wq_t);
    cudaGetSymbolAddress((void**)&p_wkv, g_wkv_t);
    cudaGetSymbolAddress((void**)&p_wout, g_wout_t);
    cudaGetSymbolAddress((void**)&p_media, g_media_t);

    cudaFuncSetAttribute(tf32gemm_pipe, cudaFuncAttributeMaxDynamicSharedMemorySize, SMEM_BYTES);

    // 0. weights: transpose to [n][k] + tf32 round + k-permute; media: round + permute
    wtrans_kernel<<<dim3(INNER / 32, DIM / 32), 256>>>(Wq, p_wq, DIM, INNER);
    wtrans_kernel<<<dim3(2 * INNER / 32, DIM_VIS / 32), 256>>>(Wkv, p_wkv, DIM_VIS, 2 * INNER);
    wtrans_kernel<<<dim3(DIM / 32, INNER / 32), 256>>>(Wout, p_wout, INNER, DIM);
    cvt_perm_kernel<<<(KVROWS * DIM_VIS / 4) / 256, 256>>>(media, p_media, KVROWS * DIM_VIS / 4);

    // 1. LayerNorm
    ln_kernel<<<ROWS, 256>>>(x, gamma, beta);

    // 2. kv = media_flat @ Wkv   (2048 x 1024 x 1024)
    tf32gemm_pipe<<<dim3((2 * INNER) / 128, KVROWS / 128), 256, SMEM_BYTES>>>(
        p_media, p_wkv, p_kv, KVROWS, 2 * INNER, DIM_VIS);
    // 3. q = xn @ Wq             (8192 x 512 x 2048)
    tf32gemm_pipe<<<dim3(INNER / 128, ROWS / 128), 256, SMEM_BYTES>>>(
        p_xn, p_wq, p_q, ROWS, INNER, DIM);
    // 4. query grouping by text_time
    build_lists2<<<BATCH, 256>>>(locs);

    // 5. masked chunk attention
    attn_kernel<<<BATCH * HEADS * 9, 256>>>();

    // 6. out = ao @ Wout         (8192 x 2048 x 512)
    tf32gemm_pipe<<<dim3(DIM / 128, ROWS / 128), 256, SMEM_BYTES>>>(
        p_ao, p_wout, out, ROWS, DIM, INNER);
}